// round 4
// baseline (speedup 1.0000x reference)
#include <cuda_runtime.h>
#include <math.h>
#include <complex>

#define TT 50
#define NB 50
#define NC 4096
#define NCH (NB*NC)          // 204800 channels
#define NCH2 (NCH/2)         // 102400 packed channel-pairs
#define PADLEN 49
#define EXTLEN 148
#define RS 149               // smem row stride in u64 (148 used + 1 pad -> conflict-free)
#define THREADS 128

typedef unsigned long long u64;

struct Coefs { float c[2][2][5]; }; // [band][section][b0, a1, a2, zi0, zi1]

// per-channel-pair packed (1/s_lo, 1/s_hi); 2 bands x 102400 pairs = 1.6 MB
__device__ __align__(16) u64 g_is[2][NCH2];

// ---------------- packed f32x2 helpers (sm_103a) ----------------
__device__ __forceinline__ u64 pk2(float lo, float hi) {
    u64 d; asm("mov.b64 %0, {%1, %2};" : "=l"(d) : "f"(lo), "f"(hi)); return d;
}
__device__ __forceinline__ void upk2(u64 v, float& lo, float& hi) {
    asm("mov.b64 {%0, %1}, %2;" : "=f"(lo), "=f"(hi) : "l"(v));
}
__device__ __forceinline__ u64 fma2(u64 a, u64 b, u64 c) {
    u64 d; asm("fma.rn.f32x2 %0, %1, %2, %3;" : "=l"(d) : "l"(a), "l"(b), "l"(c)); return d;
}
__device__ __forceinline__ u64 add2(u64 a, u64 b) {
    u64 d; asm("add.rn.f32x2 %0, %1, %2;" : "=l"(d) : "l"(a), "l"(b)); return d;
}
__device__ __forceinline__ u64 mul2(u64 a, u64 b) {
    u64 d; asm("mul.rn.f32x2 %0, %1, %2;" : "=l"(d) : "l"(a), "l"(b)); return d;
}
__device__ __forceinline__ u64 neg2(u64 a) { return a ^ 0x8000000080000000ull; }

// DF2T biquad step with b1 = 0, b2 = -b0 (always true for these bandpass sections):
//   y  = b0*x + z0
//   z0 = z1 - a1*y
//   z1 = -b0*x - a2*y
__device__ __forceinline__ u64 secstep(u64 X, u64 b0p, u64 na1p, u64 na2p, u64& z0, u64& z1) {
    u64 u = mul2(b0p, X);
    u64 y = add2(u, z0);
    z0 = fma2(na1p, y, z1);
    z1 = fma2(na2p, y, neg2(u));
    return y;
}

__global__ void __launch_bounds__(THREADS, 1)
filtfilt_kernel(const u64* __restrict__ xin, u64* __restrict__ yout, Coefs cf)
{
    extern __shared__ u64 sm[];
    const int tid = threadIdx.x;
    u64* E = sm + tid * RS;                       // per-thread private row, no barriers needed
    const int band = blockIdx.y;
    const unsigned gch = blockIdx.x * (unsigned)THREADS + tid;   // packed channel-pair index

    // broadcast coefficients into packed pairs
    const float b00 = cf.c[band][0][0], a01 = cf.c[band][0][1], a02 = cf.c[band][0][2];
    const float z00c = cf.c[band][0][3], z01c = cf.c[band][0][4];
    const float b10 = cf.c[band][1][0], a11 = cf.c[band][1][1], a12 = cf.c[band][1][2];
    const float z10c = cf.c[band][1][3], z11c = cf.c[band][1][4];

    const u64 b0p0 = pk2(b00, b00), na1p0 = pk2(-a01, -a01), na2p0 = pk2(-a02, -a02);
    const u64 b0p1 = pk2(b10, b10), na1p1 = pk2(-a11, -a11), na2p1 = pk2(-a12, -a12);
    const u64 zi00p = pk2(z00c, z00c), zi01p = pk2(z01c, z01c);
    const u64 zi10p = pk2(z10c, z10c), zi11p = pk2(z11c, z11c);

    // ---- load input (coalesced 64-bit) into middle of ext buffer ----
#pragma unroll 5
    for (int t = 0; t < TT; t++)
        E[PADLEN + t] = xin[(unsigned)t * NCH2 + gch];

    // ---- odd extension: ext[i]=2x0-x[49-i], ext[99+j]=2x49-x[48-j] ----
    const u64 x0 = E[PADLEN], xT = E[PADLEN + TT - 1];
    const u64 tw0 = add2(x0, x0), twT = add2(xT, xT);
#pragma unroll 7
    for (int i = 0; i < PADLEN; i++)
        E[i] = add2(tw0, neg2(E[98 - i]));
#pragma unroll 7
    for (int j = 0; j < PADLEN; j++)
        E[99 + j] = add2(twT, neg2(E[97 - j]));

    // ---- forward pass (in place). Outputs for k < 49 are never read back. ----
    const u64 e0 = E[0];
    u64 z00 = mul2(zi00p, e0), z01 = mul2(zi01p, e0);
    u64 z10 = mul2(zi10p, e0), z11 = mul2(zi11p, e0);
#pragma unroll 7
    for (int k = 0; k < PADLEN; k++) {
        u64 y0 = secstep(E[k], b0p0, na1p0, na2p0, z00, z01);
        (void)secstep(y0, b0p1, na1p1, na2p1, z10, z11);
    }
#pragma unroll 4
    for (int k = PADLEN; k < EXTLEN; k++) {
        u64 y0 = secstep(E[k], b0p0, na1p0, na2p0, z00, z01);
        E[k] = secstep(y0, b0p1, na1p1, na2p1, z10, z11);
    }

    // ---- backward pass over reversed forward output; only steps 49..98 kept ----
    const u64 yr0 = E[EXTLEN - 1];
    z00 = mul2(zi00p, yr0); z01 = mul2(zi01p, yr0);
    z10 = mul2(zi10p, yr0); z11 = mul2(zi11p, yr0);
#pragma unroll 7
    for (int k = 0; k < PADLEN; k++) {
        u64 y0 = secstep(E[147 - k], b0p0, na1p0, na2p0, z00, z01);
        (void)secstep(y0, b0p1, na1p1, na2p1, z10, z11);
    }
    u64 sum = 0ull;                // 0ull == packed (0.0f, 0.0f)
#pragma unroll 5
    for (int k = PADLEN; k <= 98; k++) {
        u64 y0 = secstep(E[147 - k], b0p0, na1p0, na2p0, z00, z01);
        u64 y1 = secstep(y0, b0p1, na1p1, na2p1, z10, z11);
        E[147 - k] = y1;           // final y[t] lands at E[49+t] (t = 98-k)
        sum = add2(sum, y1);
    }

    // ---- demean (channel's own mean over time), two-pass variance (ddof=1) ----
    float sl, sh;
    upk2(sum, sl, sh);
    const u64 mp = pk2(sl * 0.02f, sh * 0.02f);

    u64* obase = yout + (unsigned)band * (TT * NCH2) + gch;
    u64 sq = 0ull;
#pragma unroll 5
    for (int t = 0; t < TT; t++) {
        u64 d = add2(E[PADLEN + t], neg2(mp));
        sq = fma2(d, d, sq);
        obase[(unsigned)t * NCH2] = d;     // demeaned y; scaled by kernel 2
    }
    float ql, qh;
    upk2(sq, ql, qh);
    const float il = rsqrtf(ql * (1.0f / 49.0f));
    const float ih = rsqrtf(qh * (1.0f / 49.0f));
    g_is[band][gch] = pk2(il, ih);
}

// Reference's _tensor_zscore broadcasts m[:,None,:] / s[:,None,:] ([B,1,C]) against
// [T,B,C] with T==B: out[t,b,c] = (ydm[t,b,c] - m2[t,c]) / s[t,c]. m2 is the residual
// mean of an already-demeaned channel (exactly 0 in exact arithmetic, ~1e-7 in f32),
// so: out[t,b,c] = ydm[t,b,c] * (1/s)[channel (b=t, c)].
__global__ void __launch_bounds__(256)
scale_kernel(u64* __restrict__ out)
{
    const unsigned p = blockIdx.x * 256u + threadIdx.x;    // 5,120,000 threads
    const unsigned i2 = p * 2u;                            // even u64 index
    const unsigned band = i2 / (unsigned)(TT * NCH2);
    const unsigned rem  = i2 - band * (unsigned)(TT * NCH2);
    const unsigned t    = rem / (unsigned)NCH2;
    const unsigned q    = rem - t * (unsigned)NCH2;        // b*2048 + cpair (even)
    const unsigned cp   = q & 2047u;                       // cpair (even)

    ulonglong2 v = *reinterpret_cast<ulonglong2*>(out + i2);
    const ulonglong2 s = *reinterpret_cast<const ulonglong2*>(&g_is[band][t * 2048u + cp]);
    v.x = mul2(v.x, s.x);
    v.y = mul2(v.y, s.y);
    *reinterpret_cast<ulonglong2*>(out + i2) = v;
}

// ---------------- host: scipy-equivalent butter bandpass + sosfilt_zi ----------------
static void design_band(double w1, double w2, float sec[2][5])
{
    const int n = 2;
    const double fs = 2.0, fs2 = 4.0;
    const double PI = 3.14159265358979323846;
    double warped0 = 2.0 * fs * tan(PI * w1 / fs);
    double warped1 = 2.0 * fs * tan(PI * w2 / fs);
    double bw = warped1 - warped0;
    double wo = sqrt(warped0 * warped1);

    std::complex<double> plp[2], disc[2], p_bp[4];
    for (int k = 1; k <= n; k++) {
        std::complex<double> p = -std::exp(std::complex<double>(0.0, PI * (2 * k - 1) / (2.0 * n)));
        plp[k - 1] = p * (bw / 2.0);
        disc[k - 1] = std::sqrt(plp[k - 1] * plp[k - 1] - std::complex<double>(wo * wo, 0.0));
    }
    p_bp[0] = plp[0] + disc[0]; p_bp[1] = plp[1] + disc[1];
    p_bp[2] = plp[0] - disc[0]; p_bp[3] = plp[1] - disc[1];

    std::complex<double> prod(1.0, 0.0);
    for (int i = 0; i < 4; i++) prod *= (std::complex<double>(fs2, 0.0) - p_bp[i]);
    double gain = pow(bw, n) * pow(fs2, n) / prod.real();

    std::complex<double> pos[2]; int np = 0;
    for (int i = 0; i < 4; i++) {
        std::complex<double> pd = (std::complex<double>(fs2, 0.0) + p_bp[i]) /
                                  (std::complex<double>(fs2, 0.0) - p_bp[i]);
        if (pd.imag() > 0.0 && np < 2) pos[np++] = pd;
    }

    double sb[2][3], sa[2][3];
    for (int i = 0; i < 2; i++) {
        double g = (i == 0) ? gain : 1.0;
        sb[i][0] = g; sb[i][1] = 0.0; sb[i][2] = -g;
        sa[i][0] = 1.0; sa[i][1] = -2.0 * pos[i].real(); sa[i][2] = std::norm(pos[i]);
    }
    // sosfilt_zi
    double scale = 1.0;
    for (int s = 0; s < 2; s++) {
        double b0 = sb[s][0], b1 = sb[s][1], b2 = sb[s][2];
        double a1 = sa[s][1], a2 = sa[s][2];
        double B0 = b1 - a1 * b0, B1 = b2 - a2 * b0, det = 1.0 + a1 + a2;
        double zz0 = scale * (B0 + B1) / det;
        double zz1 = scale * ((1.0 + a1) * B1 - a2 * B0) / det;
        scale *= (b0 + b1 + b2) / (1.0 + a1 + a2);
        sec[s][0] = (float)b0; sec[s][1] = (float)a1; sec[s][2] = (float)a2;
        sec[s][3] = (float)zz0; sec[s][4] = (float)zz1;
    }
}

extern "C" void kernel_launch(void* const* d_in, const int* in_sizes, int n_in,
                              void* d_out, int out_size)
{
    (void)in_sizes; (void)n_in; (void)out_size;
    Coefs cf;
    design_band(0.05, 0.15, cf.c[0]);
    design_band(0.20, 0.40, cf.c[1]);

    const int smem = THREADS * RS * 8;   // 152,576 B
    cudaFuncSetAttribute(filtfilt_kernel, cudaFuncAttributeMaxDynamicSharedMemorySize, smem);

    dim3 grid(NCH2 / THREADS, 2);        // (800, 2)
    filtfilt_kernel<<<grid, THREADS, smem>>>((const u64*)d_in[0], (u64*)d_out, cf);

    // rescale: out[t,b,c] *= 1/s[channel (b=t, c)]  (2*TT*NCH2 u64 / 2 per thread)
    scale_kernel<<<(2 * TT * NCH2 / 2) / 256, 256>>>((u64*)d_out);
}

// round 5
// speedup vs baseline: 1.0033x; 1.0033x over previous
#include <cuda_runtime.h>
#include <math.h>
#include <complex>

#define TT 50
#define NB 50
#define NC 4096
#define NCH (NB*NC)          // 204800 channels
#define NCH2 (NCH/2)         // 102400 packed channel-pairs
#define PADLEN 49
#define EXTLEN 148
#define RS 149               // smem row stride in u64 (148 used + 1 pad -> conflict-free)
#define THREADS 128

typedef unsigned long long u64;

struct Coefs { float c[2][2][5]; }; // [band][section][b0, a1, a2, zi0, zi1]

// per-channel-pair packed (1/s_lo, 1/s_hi); 2 bands x 102400 pairs = 1.6 MB
__device__ __align__(16) u64 g_is[2][NCH2];

// ---------------- packed f32x2 helpers (sm_103a) ----------------
__device__ __forceinline__ u64 pk2(float lo, float hi) {
    u64 d; asm("mov.b64 %0, {%1, %2};" : "=l"(d) : "f"(lo), "f"(hi)); return d;
}
__device__ __forceinline__ void upk2(u64 v, float& lo, float& hi) {
    asm("mov.b64 {%0, %1}, %2;" : "=f"(lo), "=f"(hi) : "l"(v));
}
__device__ __forceinline__ u64 fma2(u64 a, u64 b, u64 c) {
    u64 d; asm("fma.rn.f32x2 %0, %1, %2, %3;" : "=l"(d) : "l"(a), "l"(b), "l"(c)); return d;
}
__device__ __forceinline__ u64 add2(u64 a, u64 b) {
    u64 d; asm("add.rn.f32x2 %0, %1, %2;" : "=l"(d) : "l"(a), "l"(b)); return d;
}
__device__ __forceinline__ u64 mul2(u64 a, u64 b) {
    u64 d; asm("mul.rn.f32x2 %0, %1, %2;" : "=l"(d) : "l"(a), "l"(b)); return d;
}
__device__ __forceinline__ u64 neg2(u64 a) { return a ^ 0x8000000080000000ull; }

// DF2T biquad step with b1 = 0, b2 = -b0 (always true for these bandpass sections):
//   y  = b0*x + z0
//   z0 = z1 - a1*y
//   z1 = -b0*x - a2*y
__device__ __forceinline__ u64 secstep(u64 X, u64 b0p, u64 na1p, u64 na2p, u64& z0, u64& z1) {
    u64 u = mul2(b0p, X);
    u64 y = add2(u, z0);
    z0 = fma2(na1p, y, z1);
    z1 = fma2(na2p, y, neg2(u));
    return y;
}

__global__ void __launch_bounds__(THREADS, 1)
filtfilt_kernel(const u64* __restrict__ xin, u64* __restrict__ yout, Coefs cf)
{
    extern __shared__ u64 sm[];
    const int tid = threadIdx.x;
    u64* E = sm + tid * RS;                       // per-thread private row, no barriers needed
    const int band = blockIdx.y;
    const unsigned gch = blockIdx.x * (unsigned)THREADS + tid;   // packed channel-pair index

    // broadcast coefficients into packed pairs
    const float b00 = cf.c[band][0][0], a01 = cf.c[band][0][1], a02 = cf.c[band][0][2];
    const float z00c = cf.c[band][0][3], z01c = cf.c[band][0][4];
    const float b10 = cf.c[band][1][0], a11 = cf.c[band][1][1], a12 = cf.c[band][1][2];
    const float z10c = cf.c[band][1][3], z11c = cf.c[band][1][4];

    const u64 b0p0 = pk2(b00, b00), na1p0 = pk2(-a01, -a01), na2p0 = pk2(-a02, -a02);
    const u64 b0p1 = pk2(b10, b10), na1p1 = pk2(-a11, -a11), na2p1 = pk2(-a12, -a12);
    const u64 zi00p = pk2(z00c, z00c), zi01p = pk2(z01c, z01c);
    const u64 zi10p = pk2(z10c, z10c), zi11p = pk2(z11c, z11c);

    // ---- load input (coalesced 64-bit) into middle of ext buffer ----
#pragma unroll 5
    for (int t = 0; t < TT; t++)
        E[PADLEN + t] = xin[(unsigned)t * NCH2 + gch];

    // ---- odd extension: ext[i]=2x0-x[49-i], ext[99+j]=2x49-x[48-j] ----
    const u64 x0 = E[PADLEN], xT = E[PADLEN + TT - 1];
    const u64 tw0 = add2(x0, x0), twT = add2(xT, xT);
#pragma unroll 7
    for (int i = 0; i < PADLEN; i++)
        E[i] = add2(tw0, neg2(E[98 - i]));
#pragma unroll 7
    for (int j = 0; j < PADLEN; j++)
        E[99 + j] = add2(twT, neg2(E[97 - j]));

    // ---- forward pass (in place). Outputs for k < 49 are never read back. ----
    const u64 e0 = E[0];
    u64 z00 = mul2(zi00p, e0), z01 = mul2(zi01p, e0);
    u64 z10 = mul2(zi10p, e0), z11 = mul2(zi11p, e0);
#pragma unroll 7
    for (int k = 0; k < PADLEN; k++) {
        u64 y0 = secstep(E[k], b0p0, na1p0, na2p0, z00, z01);
        (void)secstep(y0, b0p1, na1p1, na2p1, z10, z11);
    }
#pragma unroll 4
    for (int k = PADLEN; k < EXTLEN; k++) {
        u64 y0 = secstep(E[k], b0p0, na1p0, na2p0, z00, z01);
        E[k] = secstep(y0, b0p1, na1p1, na2p1, z10, z11);
    }

    // ---- backward pass over reversed forward output; only steps 49..98 kept ----
    const u64 yr0 = E[EXTLEN - 1];
    z00 = mul2(zi00p, yr0); z01 = mul2(zi01p, yr0);
    z10 = mul2(zi10p, yr0); z11 = mul2(zi11p, yr0);
#pragma unroll 7
    for (int k = 0; k < PADLEN; k++) {
        u64 y0 = secstep(E[147 - k], b0p0, na1p0, na2p0, z00, z01);
        (void)secstep(y0, b0p1, na1p1, na2p1, z10, z11);
    }
    u64 sum = 0ull;                // 0ull == packed (0.0f, 0.0f)
#pragma unroll 5
    for (int k = PADLEN; k <= 98; k++) {
        u64 y0 = secstep(E[147 - k], b0p0, na1p0, na2p0, z00, z01);
        u64 y1 = secstep(y0, b0p1, na1p1, na2p1, z10, z11);
        E[147 - k] = y1;           // final y[t] lands at E[49+t] (t = 98-k)
        sum = add2(sum, y1);
    }

    // ---- demean (channel's own mean over time), two-pass variance (ddof=1) ----
    float sl, sh;
    upk2(sum, sl, sh);
    const u64 mp = pk2(sl * 0.02f, sh * 0.02f);

    u64* obase = yout + (unsigned)band * (TT * NCH2) + gch;
    u64 sq = 0ull;
#pragma unroll 5
    for (int t = 0; t < TT; t++) {
        u64 d = add2(E[PADLEN + t], neg2(mp));
        sq = fma2(d, d, sq);
        obase[(unsigned)t * NCH2] = d;     // demeaned y; scaled by kernel 2
    }
    float ql, qh;
    upk2(sq, ql, qh);
    const float il = rsqrtf(ql * (1.0f / 49.0f));
    const float ih = rsqrtf(qh * (1.0f / 49.0f));
    g_is[band][gch] = pk2(il, ih);
}

// Reference's _tensor_zscore broadcasts m[:,None,:] / s[:,None,:] ([B,1,C]) against
// [T,B,C] with T==B: out[t,b,c] = (ydm[t,b,c] - m2[t,c]) / s[t,c]. m2 is the residual
// mean of an already-demeaned channel (exactly 0 in exact arithmetic, ~1e-7 in f32),
// so: out[t,b,c] = ydm[t,b,c] * (1/s)[channel (b=t, c)].
__global__ void __launch_bounds__(256)
scale_kernel(u64* __restrict__ out)
{
    const unsigned p = blockIdx.x * 256u + threadIdx.x;    // 5,120,000 threads
    const unsigned i2 = p * 2u;                            // even u64 index
    const unsigned band = i2 / (unsigned)(TT * NCH2);
    const unsigned rem  = i2 - band * (unsigned)(TT * NCH2);
    const unsigned t    = rem / (unsigned)NCH2;
    const unsigned q    = rem - t * (unsigned)NCH2;        // b*2048 + cpair (even)
    const unsigned cp   = q & 2047u;                       // cpair (even)

    ulonglong2 v = *reinterpret_cast<ulonglong2*>(out + i2);
    const ulonglong2 s = *reinterpret_cast<const ulonglong2*>(&g_is[band][t * 2048u + cp]);
    v.x = mul2(v.x, s.x);
    v.y = mul2(v.y, s.y);
    *reinterpret_cast<ulonglong2*>(out + i2) = v;
}

// ---------------- host: scipy-equivalent butter bandpass + sosfilt_zi ----------------
static void design_band(double w1, double w2, float sec[2][5])
{
    const int n = 2;
    const double fs = 2.0, fs2 = 4.0;
    const double PI = 3.14159265358979323846;
    double warped0 = 2.0 * fs * tan(PI * w1 / fs);
    double warped1 = 2.0 * fs * tan(PI * w2 / fs);
    double bw = warped1 - warped0;
    double wo = sqrt(warped0 * warped1);

    std::complex<double> plp[2], disc[2], p_bp[4];
    for (int k = 1; k <= n; k++) {
        std::complex<double> p = -std::exp(std::complex<double>(0.0, PI * (2 * k - 1) / (2.0 * n)));
        plp[k - 1] = p * (bw / 2.0);
        disc[k - 1] = std::sqrt(plp[k - 1] * plp[k - 1] - std::complex<double>(wo * wo, 0.0));
    }
    p_bp[0] = plp[0] + disc[0]; p_bp[1] = plp[1] + disc[1];
    p_bp[2] = plp[0] - disc[0]; p_bp[3] = plp[1] - disc[1];

    std::complex<double> prod(1.0, 0.0);
    for (int i = 0; i < 4; i++) prod *= (std::complex<double>(fs2, 0.0) - p_bp[i]);
    double gain = pow(bw, n) * pow(fs2, n) / prod.real();

    std::complex<double> pos[2]; int np = 0;
    for (int i = 0; i < 4; i++) {
        std::complex<double> pd = (std::complex<double>(fs2, 0.0) + p_bp[i]) /
                                  (std::complex<double>(fs2, 0.0) - p_bp[i]);
        if (pd.imag() > 0.0 && np < 2) pos[np++] = pd;
    }

    double sb[2][3], sa[2][3];
    for (int i = 0; i < 2; i++) {
        double g = (i == 0) ? gain : 1.0;
        sb[i][0] = g; sb[i][1] = 0.0; sb[i][2] = -g;
        sa[i][0] = 1.0; sa[i][1] = -2.0 * pos[i].real(); sa[i][2] = std::norm(pos[i]);
    }
    // sosfilt_zi
    double scale = 1.0;
    for (int s = 0; s < 2; s++) {
        double b0 = sb[s][0], b1 = sb[s][1], b2 = sb[s][2];
        double a1 = sa[s][1], a2 = sa[s][2];
        double B0 = b1 - a1 * b0, B1 = b2 - a2 * b0, det = 1.0 + a1 + a2;
        double zz0 = scale * (B0 + B1) / det;
        double zz1 = scale * ((1.0 + a1) * B1 - a2 * B0) / det;
        scale *= (b0 + b1 + b2) / (1.0 + a1 + a2);
        sec[s][0] = (float)b0; sec[s][1] = (float)a1; sec[s][2] = (float)a2;
        sec[s][3] = (float)zz0; sec[s][4] = (float)zz1;
    }
}

extern "C" void kernel_launch(void* const* d_in, const int* in_sizes, int n_in,
                              void* d_out, int out_size)
{
    (void)in_sizes; (void)n_in; (void)out_size;
    Coefs cf;
    design_band(0.05, 0.15, cf.c[0]);
    design_band(0.20, 0.40, cf.c[1]);

    const int smem = THREADS * RS * 8;   // 152,576 B
    cudaFuncSetAttribute(filtfilt_kernel, cudaFuncAttributeMaxDynamicSharedMemorySize, smem);

    dim3 grid(NCH2 / THREADS, 2);        // (800, 2)
    filtfilt_kernel<<<grid, THREADS, smem>>>((const u64*)d_in[0], (u64*)d_out, cf);

    // rescale: out[t,b,c] *= 1/s[channel (b=t, c)]  (2*TT*NCH2 u64 / 2 per thread)
    scale_kernel<<<(2 * TT * NCH2 / 2) / 256, 256>>>((u64*)d_out);
}

// round 6
// speedup vs baseline: 1.6154x; 1.6102x over previous
#include <cuda_runtime.h>
#include <math.h>
#include <complex>

#define TT 50
#define NB 50
#define NC 4096
#define NCH (NB*NC)          // 204800 channels
#define NCH2 (NCH/2)         // 102400 packed channel-pairs
#define PADLEN 49
#define RS 99                // smem row stride in u64 (exact live set; stride 99 -> conflict-free)
#define THREADS 256

typedef unsigned long long u64;

struct Coefs { float c[2][2][5]; }; // [band][section][b0, a1, a2, zi0, zi1]

// per-channel-pair packed (1/s_lo, 1/s_hi); 2 bands x 102400 pairs = 1.6 MB
__device__ __align__(16) u64 g_is[2][NCH2];

// ---------------- packed f32x2 helpers (sm_103a) ----------------
__device__ __forceinline__ u64 pk2(float lo, float hi) {
    u64 d; asm("mov.b64 %0, {%1, %2};" : "=l"(d) : "f"(lo), "f"(hi)); return d;
}
__device__ __forceinline__ void upk2(u64 v, float& lo, float& hi) {
    asm("mov.b64 {%0, %1}, %2;" : "=f"(lo), "=f"(hi) : "l"(v));
}
__device__ __forceinline__ u64 fma2(u64 a, u64 b, u64 c) {
    u64 d; asm("fma.rn.f32x2 %0, %1, %2, %3;" : "=l"(d) : "l"(a), "l"(b), "l"(c)); return d;
}
__device__ __forceinline__ u64 add2(u64 a, u64 b) {
    u64 d; asm("add.rn.f32x2 %0, %1, %2;" : "=l"(d) : "l"(a), "l"(b)); return d;
}
__device__ __forceinline__ u64 mul2(u64 a, u64 b) {
    u64 d; asm("mul.rn.f32x2 %0, %1, %2;" : "=l"(d) : "l"(a), "l"(b)); return d;
}
__device__ __forceinline__ u64 neg2(u64 a) { return a ^ 0x8000000080000000ull; }

// DF2T biquad step with b1 = 0, b2 = -b0 (always true for these bandpass sections):
//   y  = b0*x + z0 ; z0 = z1 - a1*y ; z1 = -b0*x - a2*y
__device__ __forceinline__ u64 secstep(u64 X, u64 b0p, u64 na1p, u64 na2p, u64& z0, u64& z1) {
    u64 u = mul2(b0p, X);
    u64 y = add2(u, z0);
    z0 = fma2(na1p, y, z1);
    z1 = fma2(na2p, y, neg2(u));
    return y;
}

#define STEP2(X) do { u64 _y0 = secstep((X), b0p0, na1p0, na2p0, z00, z01); \
                      (void)secstep(_y0, b0p1, na1p1, na2p1, z10, z11); } while (0)
#define STEP2W(X, W) do { u64 _y0 = secstep((X), b0p0, na1p0, na2p0, z00, z01); \
                          (W) = secstep(_y0, b0p1, na1p1, na2p1, z10, z11); } while (0)

// Buffer layout (per-thread, 99 u64 slots):
//   x[j]            -> B[49+j]            (j = 0..49)
//   fwd w_k         -> B[k-49]  k=49..97  (slots 0..48, previously empty)
//                      B[98]    k=98      (over dead x[49])
//                      B[196-k] k=99..147 (over just-consumed x[147-k])
//   final y[t]      -> B[t] t=0..48, y[49] -> B[98] (slot freed by backward read)
__global__ void __launch_bounds__(THREADS, 1)
filtfilt_kernel(const u64* __restrict__ xin, u64* __restrict__ yout, Coefs cf)
{
    extern __shared__ u64 sm[];
    const int tid = threadIdx.x;
    u64* B = sm + tid * RS;                       // per-thread private row, no barriers
    const int band = blockIdx.y;
    const unsigned gch = blockIdx.x * (unsigned)THREADS + tid;   // packed channel-pair index

    const float b00 = cf.c[band][0][0], a01 = cf.c[band][0][1], a02 = cf.c[band][0][2];
    const float z00c = cf.c[band][0][3], z01c = cf.c[band][0][4];
    const float b10 = cf.c[band][1][0], a11 = cf.c[band][1][1], a12 = cf.c[band][1][2];
    const float z10c = cf.c[band][1][3], z11c = cf.c[band][1][4];

    const u64 b0p0 = pk2(b00, b00), na1p0 = pk2(-a01, -a01), na2p0 = pk2(-a02, -a02);
    const u64 b0p1 = pk2(b10, b10), na1p1 = pk2(-a11, -a11), na2p1 = pk2(-a12, -a12);
    const u64 zi00p = pk2(z00c, z00c), zi01p = pk2(z01c, z01c);
    const u64 zi10p = pk2(z10c, z10c), zi11p = pk2(z11c, z11c);

    // ---- load input (coalesced 64-bit): x[t] -> B[49+t] ----
#pragma unroll 5
    for (int t = 0; t < TT; t++)
        B[PADLEN + t] = xin[(unsigned)t * NCH2 + gch];

    const u64 x0 = B[PADLEN], xT = B[PADLEN + TT - 1];
    const u64 tw0 = add2(x0, x0), twT = add2(xT, xT);

    // ---- forward pass; extensions computed on the fly ----
    const u64 e0 = add2(tw0, neg2(B[98]));        // ext[0] = 2x0 - x[49]
    u64 z00 = mul2(zi00p, e0), z01 = mul2(zi01p, e0);
    u64 z10 = mul2(zi10p, e0), z11 = mul2(zi11p, e0);

    u64 xv = B[98];                               // x[49] (input of warmup step 0)
    // warmup k=0..48: ext[k] = 2x0 - x[49-k]; outputs discarded
#pragma unroll 7
    for (int k = 0; k < 49; k++) {
        u64 cur = xv;
        xv = B[97 - k];                           // next: x[48-k]; at k=48 -> B[49]=x[0]
        STEP2(add2(tw0, neg2(cur)));
    }
    // main k=49..97: input x[k-49] (prefetched), write w_k -> B[k-49]
#pragma unroll 7
    for (int k = 49; k < 98; k++) {
        u64 cur = xv;
        xv = B[k + 1];                            // next x; at k=97 -> B[98]=x[49]
        u64 w; STEP2W(cur, w);
        B[k - 49] = w;
    }
    // k=98: input x[49] (prefetched), write w_98 -> B[98]
    {
        u64 cur = xv;
        xv = B[97];                               // x[48], input basis for k=99
        u64 w; STEP2W(cur, w);
        B[98] = w;
    }
    // tail k=99..147: ext[k] = 2x49 - x[147-k]; write w_k -> B[196-k]
#pragma unroll 7
    for (int k = 99; k < 148; k++) {
        u64 cur = xv;
        xv = B[195 - k];                          // next x[146-k]; harmless read at k=147
        u64 w; STEP2W(add2(twT, neg2(cur)), w);
        B[196 - k] = w;
    }

    // ---- backward pass over reversed forward output ----
    u64 rv = B[49];                               // w_147
    const u64 yr0 = rv;
    z00 = mul2(zi00p, yr0); z01 = mul2(zi01p, yr0);
    z10 = mul2(zi10p, yr0); z11 = mul2(zi11p, yr0);

    // warmup m=0..48: consume w_{147-m} at B[49+m]; outputs discarded
#pragma unroll 7
    for (int m = 0; m < 49; m++) {
        u64 cur = rv;
        rv = B[50 + m];                           // next; at m=48 -> B[98]=w_98
        STEP2(cur);
    }
    u64 sum = 0ull;
    // m=49: consume w_98 at B[98]; produce y[49] -> B[98]
    {
        u64 cur = rv;
        rv = B[48];                               // w_97 (next)
        u64 y1; STEP2W(cur, y1);
        B[98] = y1;
        sum = add2(sum, y1);
    }
    // m=50..98: consume w_{147-m} at B[98-m]; produce y[98-m] -> same slot
#pragma unroll 7
    for (int m = 50; m < 99; m++) {
        u64 cur = rv;
        rv = B[97 - m];                           // next; harmless read at m=98 (B[-1]? no: 97-98=-1)
        u64 y1; STEP2W(cur, y1);
        B[98 - m] = y1;
        sum = add2(sum, y1);
    }

    // ---- demean (channel's own mean), two-pass variance (ddof=1) ----
    float sl, sh;
    upk2(sum, sl, sh);
    const u64 mp = pk2(sl * 0.02f, sh * 0.02f);

    u64* obase = yout + (unsigned)band * (TT * NCH2) + gch;
    u64 sq = 0ull;
#pragma unroll 7
    for (int t = 0; t < 49; t++) {
        u64 d = add2(B[t], neg2(mp));
        sq = fma2(d, d, sq);
        obase[(unsigned)t * NCH2] = d;
    }
    {
        u64 d = add2(B[98], neg2(mp));            // y[49]
        sq = fma2(d, d, sq);
        obase[49u * NCH2] = d;
    }
    float ql, qh;
    upk2(sq, ql, qh);
    g_is[band][gch] = pk2(rsqrtf(ql * (1.0f / 49.0f)), rsqrtf(qh * (1.0f / 49.0f)));
}

// Reference's _tensor_zscore broadcasts m[:,None,:]/s[:,None,:] ([B,1,C]) against [T,B,C]
// with T==B: out[t,b,c] = ydm[t,b,c] * (1/s)[channel (b=t, c)] (residual mean ~0).
__global__ void __launch_bounds__(256)
scale_kernel(u64* __restrict__ out)
{
    const unsigned p = blockIdx.x * 256u + threadIdx.x;
    const unsigned i2 = p * 2u;                            // even u64 index
    const unsigned band = i2 / (unsigned)(TT * NCH2);
    const unsigned rem  = i2 - band * (unsigned)(TT * NCH2);
    const unsigned t    = rem / (unsigned)NCH2;
    const unsigned q    = rem - t * (unsigned)NCH2;
    const unsigned cp   = q & 2047u;

    ulonglong2 v = *reinterpret_cast<ulonglong2*>(out + i2);
    const ulonglong2 s = *reinterpret_cast<const ulonglong2*>(&g_is[band][t * 2048u + cp]);
    v.x = mul2(v.x, s.x);
    v.y = mul2(v.y, s.y);
    *reinterpret_cast<ulonglong2*>(out + i2) = v;
}

// ---------------- host: scipy-equivalent butter bandpass + sosfilt_zi ----------------
static void design_band(double w1, double w2, float sec[2][5])
{
    const int n = 2;
    const double fs = 2.0, fs2 = 4.0;
    const double PI = 3.14159265358979323846;
    double warped0 = 2.0 * fs * tan(PI * w1 / fs);
    double warped1 = 2.0 * fs * tan(PI * w2 / fs);
    double bw = warped1 - warped0;
    double wo = sqrt(warped0 * warped1);

    std::complex<double> plp[2], disc[2], p_bp[4];
    for (int k = 1; k <= n; k++) {
        std::complex<double> p = -std::exp(std::complex<double>(0.0, PI * (2 * k - 1) / (2.0 * n)));
        plp[k - 1] = p * (bw / 2.0);
        disc[k - 1] = std::sqrt(plp[k - 1] * plp[k - 1] - std::complex<double>(wo * wo, 0.0));
    }
    p_bp[0] = plp[0] + disc[0]; p_bp[1] = plp[1] + disc[1];
    p_bp[2] = plp[0] - disc[0]; p_bp[3] = plp[1] - disc[1];

    std::complex<double> prod(1.0, 0.0);
    for (int i = 0; i < 4; i++) prod *= (std::complex<double>(fs2, 0.0) - p_bp[i]);
    double gain = pow(bw, n) * pow(fs2, n) / prod.real();

    std::complex<double> pos[2]; int np = 0;
    for (int i = 0; i < 4; i++) {
        std::complex<double> pd = (std::complex<double>(fs2, 0.0) + p_bp[i]) /
                                  (std::complex<double>(fs2, 0.0) - p_bp[i]);
        if (pd.imag() > 0.0 && np < 2) pos[np++] = pd;
    }

    double sb[2][3], sa[2][3];
    for (int i = 0; i < 2; i++) {
        double g = (i == 0) ? gain : 1.0;
        sb[i][0] = g; sb[i][1] = 0.0; sb[i][2] = -g;
        sa[i][0] = 1.0; sa[i][1] = -2.0 * pos[i].real(); sa[i][2] = std::norm(pos[i]);
    }
    double scale = 1.0;
    for (int s = 0; s < 2; s++) {
        double b0 = sb[s][0], b1 = sb[s][1], b2 = sb[s][2];
        double a1 = sa[s][1], a2 = sa[s][2];
        double B0 = b1 - a1 * b0, B1 = b2 - a2 * b0, det = 1.0 + a1 + a2;
        double zz0 = scale * (B0 + B1) / det;
        double zz1 = scale * ((1.0 + a1) * B1 - a2 * B0) / det;
        scale *= (b0 + b1 + b2) / (1.0 + a1 + a2);
        sec[s][0] = (float)b0; sec[s][1] = (float)a1; sec[s][2] = (float)a2;
        sec[s][3] = (float)zz0; sec[s][4] = (float)zz1;
    }
}

extern "C" void kernel_launch(void* const* d_in, const int* in_sizes, int n_in,
                              void* d_out, int out_size)
{
    (void)in_sizes; (void)n_in; (void)out_size;
    Coefs cf;
    design_band(0.05, 0.15, cf.c[0]);
    design_band(0.20, 0.40, cf.c[1]);

    const int smem = THREADS * RS * 8;   // 202,752 B -> 1 CTA/SM, 8 warps
    cudaFuncSetAttribute(filtfilt_kernel, cudaFuncAttributeMaxDynamicSharedMemorySize, smem);

    dim3 grid(NCH2 / THREADS, 2);        // (400, 2)
    filtfilt_kernel<<<grid, THREADS, smem>>>((const u64*)d_in[0], (u64*)d_out, cf);

    scale_kernel<<<(2 * TT * NCH2 / 2) / 256, 256>>>((u64*)d_out);
}